// round 3
// baseline (speedup 1.0000x reference)
#include <cuda_runtime.h>

#define BB 256
#define SS 2048
#define KK 64

// Scratch (no allocations allowed in kernel_launch)
__device__ float g_M[KK * KK];   // exp(transition), row i contiguous over j
__device__ float g_logZ[BB];
__device__ float g_gold[BB];

// ---------- packed f32x2 helpers (Blackwell FFMA2 path, PTX-only) ----------
__device__ __forceinline__ unsigned long long fma2(unsigned long long a,
                                                   unsigned long long b,
                                                   unsigned long long c) {
    unsigned long long d;
    asm("fma.rn.f32x2 %0, %1, %2, %3;" : "=l"(d) : "l"(a), "l"(b), "l"(c));
    return d;
}
__device__ __forceinline__ unsigned long long add2(unsigned long long a,
                                                   unsigned long long b) {
    unsigned long long d;
    asm("add.rn.f32x2 %0, %1, %2;" : "=l"(d) : "l"(a), "l"(b));
    return d;
}
__device__ __forceinline__ float2 unpack2(unsigned long long v) {
    float2 r;
    asm("mov.b64 {%0, %1}, %2;" : "=f"(r.x), "=f"(r.y) : "l"(v));
    return r;
}
__device__ __forceinline__ unsigned long long pack2(float lo, float hi) {
    unsigned long long r;
    asm("mov.b64 %0, {%1, %2};" : "=l"(r) : "f"(lo), "f"(hi));
    return r;
}

__device__ __forceinline__ float warp_max(float v) {
#pragma unroll
    for (int o = 16; o > 0; o >>= 1)
        v = fmaxf(v, __shfl_xor_sync(0xffffffffu, v, o));
    return v;
}
__device__ __forceinline__ float warp_sum(float v) {
#pragma unroll
    for (int o = 16; o > 0; o >>= 1)
        v += __shfl_xor_sync(0xffffffffu, v, o);
    return v;
}

// ---------- kernels ----------
__global__ void init_kernel(const float* __restrict__ T) {
    int i = blockIdx.x * blockDim.x + threadIdx.x;
    if (i < KK * KK) g_M[i] = expf(T[i]);
}

__global__ __launch_bounds__(64) void forward_kernel(
    const float* __restrict__ scores,
    const float* __restrict__ source,
    const float* __restrict__ sink) {
    __shared__ __align__(16) float sE[2][KK];   // double-buffered exp(alpha - m)
    __shared__ float sWmax[2][2];               // [parity][warp] warp maxes

    const int b    = blockIdx.x;
    const int j    = threadIdx.x;      // 0..63, owns output state j
    const int warp = j >> 5;
    const int lane = j & 31;
    const float* sc = scores + (size_t)b * (SS * KK);

    // Column j of M, paired along i: Mc[p] = (M[2p][j], M[2p+1][j]). Lives in regs.
    unsigned long long Mc[32];
#pragma unroll
    for (int p = 0; p < 32; ++p)
        Mc[p] = pack2(g_M[(2 * p) * KK + j], g_M[(2 * p + 1) * KK + j]);

    const float LOG2E = 1.44269504088896340736f;
    const float LN2   = 0.69314718055994530942f;

    // alpha_0
    float a = __ldg(&source[j]) + __ldg(&sc[j]);
    {
        float wm = warp_max(a);
        if (lane == 0) { sWmax[0][warp] = wm; sWmax[1][warp] = wm; }
    }
    __syncthreads();

    for (int t = 1; t < SS; ++t) {
        const int par = t & 1;
        // Globally-consistent stale shift: max over BOTH warps' maxes from the
        // previous step. Identical on every thread (exactness of log-sum-exp
        // requires a common m), one step stale (bounded drift <= ~13, safe for
        // exp range). Keeps the loop at one barrier per step.
        float m = fmaxf(sWmax[par ^ 1][0], sWmax[par ^ 1][1]);
        float wmax = warp_max(a);
        if (lane == 0) sWmax[par][warp] = wmax;

        sE[par][j] = exp2f((a - m) * LOG2E);
        float s = __ldg(&sc[t * KK + j]);   // prefetch, hidden behind barrier+matvec
        __syncthreads();

        // acc[j] = sum_i E[i] * M[i][j], packed 2-wide, 4 accumulator chains
        const ulonglong2* e4 = reinterpret_cast<const ulonglong2*>(sE[par]);
        unsigned long long acc0 = 0ull, acc1 = 0ull, acc2 = 0ull, acc3 = 0ull;
#pragma unroll
        for (int q = 0; q < 16; q += 2) {
            ulonglong2 ea = e4[q];
            ulonglong2 eb = e4[q + 1];
            acc0 = fma2(ea.x, Mc[2 * q + 0], acc0);
            acc1 = fma2(ea.y, Mc[2 * q + 1], acc1);
            acc2 = fma2(eb.x, Mc[2 * q + 2], acc2);
            acc3 = fma2(eb.y, Mc[2 * q + 3], acc3);
        }
        acc0 = add2(acc0, acc1);
        acc2 = add2(acc2, acc3);
        acc0 = add2(acc0, acc2);
        float2 ac = unpack2(acc0);
        a = m + s + LN2 * __log2f(ac.x + ac.y);
    }

    // logZ_b = logsumexp_j(alpha + sink)
    a += __ldg(&sink[j]);
    float fm = warp_max(a);
    if (lane == 0) sWmax[0][warp] = fm;
    __syncthreads();
    float m = fmaxf(sWmax[0][0], sWmax[0][1]);
    float e = exp2f((a - m) * LOG2E);
    float ws = warp_sum(e);
    if (lane == 0) sE[0][warp] = ws;
    __syncthreads();
    if (j == 0) g_logZ[b] = m + LN2 * __log2f(sE[0][0] + sE[0][1]);
}

__global__ __launch_bounds__(256) void gold_kernel(
    const float* __restrict__ scores,
    const int* __restrict__ states,
    const float* __restrict__ T,
    const float* __restrict__ source,
    const float* __restrict__ sink) {
    __shared__ float red[256];
    const int b = blockIdx.x, tid = threadIdx.x;
    const int*   st = states + (size_t)b * SS;
    const float* sc = scores + (size_t)b * (SS * KK);

    float acc = 0.f;
    for (int t = tid; t < SS; t += 256) {
        int s0 = __ldg(&st[t]);
        acc += __ldg(&sc[t * KK + s0]);
        if (t + 1 < SS) acc += __ldg(&T[s0 * KK + __ldg(&st[t + 1])]);
    }
    red[tid] = acc;
    __syncthreads();
#pragma unroll
    for (int off = 128; off > 0; off >>= 1) {
        if (tid < off) red[tid] += red[tid + off];
        __syncthreads();
    }
    if (tid == 0)
        g_gold[b] = red[0] + __ldg(&source[__ldg(&st[0])]) +
                    __ldg(&sink[__ldg(&st[SS - 1])]);
}

__global__ __launch_bounds__(256) void finalize_kernel(float* __restrict__ out) {
    __shared__ float red[256];
    const int tid = threadIdx.x;
    red[tid] = g_logZ[tid] - g_gold[tid];
    __syncthreads();
#pragma unroll
    for (int off = 128; off > 0; off >>= 1) {
        if (tid < off) red[tid] += red[tid + off];
        __syncthreads();
    }
    if (tid == 0) *out = red[0] * (1.0f / BB);
}

extern "C" void kernel_launch(void* const* d_in, const int* in_sizes, int n_in,
                              void* d_out, int out_size) {
    const float* scores = (const float*)d_in[0];   // [B,S,K] f32
    const int*   states = (const int*)d_in[1];     // [B,S] i32
    const float* T      = (const float*)d_in[2];   // [K,K] f32
    const float* source = (const float*)d_in[3];   // [K] f32
    const float* sink   = (const float*)d_in[4];   // [K] f32
    float* out = (float*)d_out;

    init_kernel<<<16, 256>>>(T);
    forward_kernel<<<BB, KK>>>(scores, source, sink);
    gold_kernel<<<BB, 256>>>(scores, states, T, source, sink);
    finalize_kernel<<<1, 256>>>(out);
}

// round 4
// speedup vs baseline: 3.2048x; 3.2048x over previous
#include <cuda_runtime.h>

#define BB 256
#define SS 2048
#define KK 64
#define PF 8   // score prefetch depth (steps)

// Scratch (no allocations allowed in kernel_launch)
__device__ float  g_M[KK * KK];   // exp(transition), row i contiguous over j
__device__ double g_logZ[BB];
__device__ double g_gold[BB];

// ---------- packed f32x2 helpers (Blackwell FFMA2 path, PTX-only) ----------
__device__ __forceinline__ unsigned long long fma2(unsigned long long a,
                                                   unsigned long long b,
                                                   unsigned long long c) {
    unsigned long long d;
    asm("fma.rn.f32x2 %0, %1, %2, %3;" : "=l"(d) : "l"(a), "l"(b), "l"(c));
    return d;
}
__device__ __forceinline__ unsigned long long add2(unsigned long long a,
                                                   unsigned long long b) {
    unsigned long long d;
    asm("add.rn.f32x2 %0, %1, %2;" : "=l"(d) : "l"(a), "l"(b));
    return d;
}
__device__ __forceinline__ float2 unpack2(unsigned long long v) {
    float2 r;
    asm("mov.b64 {%0, %1}, %2;" : "=f"(r.x), "=f"(r.y) : "l"(v));
    return r;
}
__device__ __forceinline__ unsigned long long pack2(float lo, float hi) {
    unsigned long long r;
    asm("mov.b64 %0, {%1, %2};" : "=l"(r) : "f"(lo), "f"(hi));
    return r;
}
__device__ __forceinline__ float warp_sum(float v) {
#pragma unroll
    for (int o = 16; o > 0; o >>= 1)
        v += __shfl_xor_sync(0xffffffffu, v, o);
    return v;
}

// ---------- kernels ----------
__global__ void init_kernel(const float* __restrict__ T) {
    int i = blockIdx.x * blockDim.x + threadIdx.x;
    if (i < KK * KK) g_M[i] = expf(T[i]);
}

__global__ __launch_bounds__(64) void forward_kernel(
    const float* __restrict__ scores,
    const float* __restrict__ source,
    const float* __restrict__ sink) {
    __shared__ __align__(16) float sA[2][KK];   // double-buffered scaled exp(alpha)
    __shared__ float sRed[2];

    const int b    = blockIdx.x;
    const int j    = threadIdx.x;      // 0..63, owns output state j
    const int warp = j >> 5;
    const int lane = j & 31;
    const float* sc = scores + (size_t)b * (SS * KK);

    const float LOG2E = 1.44269504088896340736f;

    // Column j of M, paired along i: Mc[p] = (M[2p][j], M[2p+1][j]). Lives in regs.
    unsigned long long Mc[32];
#pragma unroll
    for (int p = 0; p < 32; ++p)
        Mc[p] = pack2(g_M[(2 * p) * KK + j], g_M[(2 * p + 1) * KK + j]);

    // Score prefetch ring: slot k holds s for step t with (t-1)%PF == k.
    float s_ring[PF];
#pragma unroll
    for (int k = 0; k < PF; ++k)
        s_ring[k] = __ldg(&sc[(1 + k) * KK + j]);

    // A_0[j] = exp(source[j] + s_0[j]); running exponent offset c (log2 units).
    float Acur = exp2f((__ldg(&source[j]) + __ldg(&sc[j])) * LOG2E);
    int c = 0;
    sA[0][j] = Acur;
    __syncthreads();

#pragma unroll 1
    for (int base = 1; base < SS; base += PF) {
#pragma unroll
        for (int k = 0; k < PF; ++k) {
            const int t = base + k;
            if (t >= SS) break;
            const int par = t & 1;   // base is odd -> par static per k

            // es for this step (score loaded PF steps ago); then refill ring.
            float es = exp2f(s_ring[k] * LOG2E);
            int tp = t + PF;
            tp = (tp < SS) ? tp : (SS - 1);
            s_ring[k] = __ldg(&sc[(size_t)tp * KK + j]);

            // Consistent power-of-2 rescale from exponent of A_prev[0]
            // (same shared word on every thread -> bit-identical).
            float A0v = sA[par ^ 1][0];
            int e0 = (int)((__float_as_uint(A0v) >> 23) & 0xFF);
            float scale = __uint_as_float((unsigned)(254 - e0) << 23);
            c += e0 - 127;
            float essc = es * scale;

            // acc[j] = sum_i A[i] * M[i][j], packed 2-wide, 4 accumulator chains.
            const ulonglong2* e4 = reinterpret_cast<const ulonglong2*>(sA[par ^ 1]);
            unsigned long long acc0 = 0ull, acc1 = 0ull, acc2 = 0ull, acc3 = 0ull;
#pragma unroll
            for (int q = 0; q < 16; q += 2) {
                ulonglong2 ea = e4[q];
                ulonglong2 eb = e4[q + 1];
                acc0 = fma2(ea.x, Mc[2 * q + 0], acc0);
                acc1 = fma2(ea.y, Mc[2 * q + 1], acc1);
                acc2 = fma2(eb.x, Mc[2 * q + 2], acc2);
                acc3 = fma2(eb.y, Mc[2 * q + 3], acc3);
            }
            acc0 = add2(acc0, acc1);
            acc2 = add2(acc2, acc3);
            acc0 = add2(acc0, acc2);
            float2 ac = unpack2(acc0);

            Acur = (ac.x + ac.y) * essc;
            sA[par][j] = Acur;
            __syncthreads();
        }
    }

    // logZ_b = log(sum_j A[j] * exp(sink[j])) + c*ln2
    float v = Acur * exp2f(__ldg(&sink[j]) * LOG2E);
    float ws = warp_sum(v);
    if (lane == 0) sRed[warp] = ws;
    __syncthreads();
    if (j == 0) {
        double tot = (double)(sRed[0] + sRed[1]);
        g_logZ[b] = ((double)log2f((float)tot) + (double)c) *
                    0.69314718055994530942;
    }
}

__global__ __launch_bounds__(256) void gold_kernel(
    const float* __restrict__ scores,
    const int* __restrict__ states,
    const float* __restrict__ T,
    const float* __restrict__ source,
    const float* __restrict__ sink) {
    __shared__ float red[256];
    const int b = blockIdx.x, tid = threadIdx.x;
    const int*   st = states + (size_t)b * SS;
    const float* sc = scores + (size_t)b * (SS * KK);

    float acc = 0.f;
    for (int t = tid; t < SS; t += 256) {
        int s0 = __ldg(&st[t]);
        acc += __ldg(&sc[t * KK + s0]);
        if (t + 1 < SS) acc += __ldg(&T[s0 * KK + __ldg(&st[t + 1])]);
    }
    red[tid] = acc;
    __syncthreads();
#pragma unroll
    for (int off = 128; off > 0; off >>= 1) {
        if (tid < off) red[tid] += red[tid + off];
        __syncthreads();
    }
    if (tid == 0)
        g_gold[b] = (double)red[0] + (double)__ldg(&source[__ldg(&st[0])]) +
                    (double)__ldg(&sink[__ldg(&st[SS - 1])]);
}

__global__ __launch_bounds__(256) void finalize_kernel(float* __restrict__ out) {
    __shared__ double red[256];
    const int tid = threadIdx.x;
    red[tid] = g_logZ[tid] - g_gold[tid];
    __syncthreads();
#pragma unroll
    for (int off = 128; off > 0; off >>= 1) {
        if (tid < off) red[tid] += red[tid + off];
        __syncthreads();
    }
    if (tid == 0) *out = (float)(red[0] * (1.0 / BB));
}

extern "C" void kernel_launch(void* const* d_in, const int* in_sizes, int n_in,
                              void* d_out, int out_size) {
    const float* scores = (const float*)d_in[0];   // [B,S,K] f32
    const int*   states = (const int*)d_in[1];     // [B,S] i32
    const float* T      = (const float*)d_in[2];   // [K,K] f32
    const float* source = (const float*)d_in[3];   // [K] f32
    const float* sink   = (const float*)d_in[4];   // [K] f32
    float* out = (float*)d_out;

    init_kernel<<<16, 256>>>(T);
    forward_kernel<<<BB, KK>>>(scores, source, sink);
    gold_kernel<<<BB, 256>>>(scores, states, T, source, sink);
    finalize_kernel<<<1, 256>>>(out);
}